// round 1
// baseline (speedup 1.0000x reference)
#include <cuda_runtime.h>
#include <cuda_bf16.h>
#include <cstdint>
#include <cstddef>

#define C_DIM 256
#define L_DIM 4096
#define N_DIM 64
#define M_TOT (N_DIM * L_DIM)   // 262144
#define EPSV 1e-3f
#define NS_ITERS 7

// ---------------- scratch (device globals; no allocation allowed) ----------------
__device__ float g_mean[C_DIM];              // raw channel sums
__device__ float g_sigma[C_DIM * C_DIM];     // gram sums -> sigma
__device__ float g_Y[C_DIM * C_DIM];
__device__ float g_Y2[C_DIM * C_DIM];
__device__ float g_Z[C_DIM * C_DIM];
__device__ float g_Z2[C_DIM * C_DIM];
__device__ float g_T[C_DIM * C_DIM];
__device__ float g_wm[C_DIM * C_DIM];
__device__ float g_bias[C_DIM];
__device__ float g_scal[2];                  // [0]=1/s (trace norm), [1]=rsqrt(s)

// ---------------- packed f32x2 helpers (Blackwell FFMA2) ----------------
#define PACK2(d, lo, hi) asm("mov.b64 %0, {%1, %2};" : "=l"(d) : "f"(lo), "f"(hi))
#define UNPACK2(lo, hi, s) asm("mov.b64 {%0, %1}, %2;" : "=f"(lo), "=f"(hi) : "l"(s))
#define FMA2(d, a, b) asm("fma.rn.f32x2 %0, %1, %2, %3;" : "=l"(d) : "l"(a), "l"(b), "l"(d))

// ---------------- zero accumulators (runs every replay: determinism) ----------------
__global__ void zero_kernel() {
    int idx = blockIdx.x * 256 + threadIdx.x;
    if (idx < C_DIM * C_DIM) g_sigma[idx] = 0.f;
    if (idx < C_DIM) g_mean[idx] = 0.f;
}

// ---------------- shared 128x128-tile micro-kernel (8x8 per thread, f32x2 packed) ----------------
__device__ __forceinline__ void micro_fma(const float (*As)[128], const float (*Bs)[128],
                                          unsigned long long acc[8][4], int tx, int ty) {
#pragma unroll
    for (int k = 0; k < 8; k++) {
        float4 a0 = *(const float4*)&As[k][ty * 8];
        float4 a1 = *(const float4*)&As[k][ty * 8 + 4];
        float a[8] = {a0.x, a0.y, a0.z, a0.w, a1.x, a1.y, a1.z, a1.w};
        unsigned long long ad[8];
#pragma unroll
        for (int i = 0; i < 8; i++) PACK2(ad[i], a[i], a[i]);
        float b[8];
#pragma unroll
        for (int j = 0; j < 8; j++) b[j] = Bs[k][tx + 16 * j];
        unsigned long long bp[4];
#pragma unroll
        for (int p = 0; p < 4; p++) PACK2(bp[p], b[2 * p], b[2 * p + 1]);
#pragma unroll
        for (int i = 0; i < 8; i++)
#pragma unroll
            for (int p = 0; p < 4; p++) FMA2(acc[i][p], ad[i], bp[p]);
    }
}

// ---------------- Gram: g_sigma += X Xt (K split over n), fused channel-mean ----------------
__global__ __launch_bounds__(256, 2) void gram_kernel(const float* __restrict__ X) {
    __shared__ __align__(16) float As[8][128];
    __shared__ __align__(16) float Bs[8][128];
    const int t = blockIdx.x;          // output quadrant 0..3
    const int n = blockIdx.y;          // K chunk (one batch slice)
    const int ci = (t >> 1) * 128, cj = (t & 1) * 128;
    const int tid = threadIdx.x;
    const int tx = tid & 15, ty = tid >> 4;
    const int arow = tid >> 1, aseg = tid & 1;

    const float* Ap = X + ((size_t)(n * C_DIM + ci + arow)) * L_DIM + aseg * 4;
    const float* Bp = X + ((size_t)(n * C_DIM + cj + arow)) * L_DIM + aseg * 4;

    unsigned long long acc[8][4];
#pragma unroll
    for (int i = 0; i < 8; i++)
#pragma unroll
        for (int p = 0; p < 4; p++) acc[i][p] = 0ull;
    float msum = 0.f;

    float4 va = *(const float4*)Ap;
    float4 vb = *(const float4*)Bp;
    for (int l0 = 0; l0 < L_DIM; l0 += 8) {
        __syncthreads();
        As[aseg * 4 + 0][arow] = va.x; As[aseg * 4 + 1][arow] = va.y;
        As[aseg * 4 + 2][arow] = va.z; As[aseg * 4 + 3][arow] = va.w;
        Bs[aseg * 4 + 0][arow] = vb.x; Bs[aseg * 4 + 1][arow] = vb.y;
        Bs[aseg * 4 + 2][arow] = vb.z; Bs[aseg * 4 + 3][arow] = vb.w;
        msum += va.x + va.y + va.z + va.w;
        __syncthreads();
        if (l0 + 8 < L_DIM) {
            va = *(const float4*)(Ap + l0 + 8);
            vb = *(const float4*)(Bp + l0 + 8);
        }
        micro_fma(As, Bs, acc, tx, ty);
    }

    // fused mean: A-tiles of quadrants with cj==0 cover every channel exactly once
    if ((t & 1) == 0) atomicAdd(&g_mean[ci + arow], msum);

#pragma unroll
    for (int i = 0; i < 8; i++) {
        int gi = ci + ty * 8 + i;
#pragma unroll
        for (int p = 0; p < 4; p++) {
            float lo, hi;
            UNPACK2(lo, hi, acc[i][p]);
            atomicAdd(&g_sigma[gi * C_DIM + cj + tx + 16 * (2 * p)], lo);
            atomicAdd(&g_sigma[gi * C_DIM + cj + tx + 16 * (2 * p + 1)], hi);
        }
    }
}

// ---------------- sigma = gram/m - mean meanT + eps I ----------------
__global__ void sigma_finalize_kernel() {
    int idx = blockIdx.x * 1024 + threadIdx.x;
    int i = idx >> 8, j = idx & 255;
    const float invm = 1.f / (float)M_TOT;
    float v = g_sigma[idx] * invm - (g_mean[i] * invm) * (g_mean[j] * invm);
    if (i == j) v += EPSV;
    g_sigma[idx] = v;
}

// ---------------- s = trace(sigma)/C ----------------
__global__ void trace_kernel() {
    __shared__ float red[256];
    int i = threadIdx.x;
    red[i] = g_sigma[i * (C_DIM + 1)];
    __syncthreads();
    for (int s = 128; s > 0; s >>= 1) {
        if (i < s) red[i] += red[i + s];
        __syncthreads();
    }
    if (i == 0) {
        float s = red[0] / (float)C_DIM;
        g_scal[0] = 1.f / s;
        g_scal[1] = rsqrtf(s);
    }
}

// ---------------- Newton-Schulz init: Y = sigma/s, Z = I ----------------
__global__ void ns_init_kernel() {
    int idx = blockIdx.x * 1024 + threadIdx.x;
    int i = idx >> 8, j = idx & 255;
    g_Y[idx] = g_sigma[idx] * g_scal[0];
    g_Z[idx] = (i == j) ? 1.f : 0.f;
}

// ---------------- small 256^3 GEMM tile (32x32 per block, 2x2 per thread) ----------------
__device__ __forceinline__ void small_tile(const float* __restrict__ A, const float* __restrict__ B,
                                           float acc[2][2], int i0, int j0, int tid) {
    __shared__ float As[16][32];
    __shared__ float Bs[16][32];
    const int tx = tid & 15, ty = tid >> 4;
    const int ar = tid >> 3, asg = tid & 7;
    const int br = tid >> 4, bsg = tid & 15;
    for (int k0 = 0; k0 < C_DIM; k0 += 16) {
        __syncthreads();
        float2 va = *(const float2*)&A[(i0 + ar) * C_DIM + k0 + asg * 2];
        As[asg * 2 + 0][ar] = va.x;
        As[asg * 2 + 1][ar] = va.y;
        float2 vb = *(const float2*)&B[(k0 + br) * C_DIM + j0 + bsg * 2];
        *(float2*)&Bs[br][bsg * 2] = vb;
        __syncthreads();
#pragma unroll
        for (int k = 0; k < 16; k++) {
            float a0 = As[k][ty * 2], a1 = As[k][ty * 2 + 1];
            float b0 = Bs[k][tx * 2], b1 = Bs[k][tx * 2 + 1];
            acc[0][0] = fmaf(a0, b0, acc[0][0]);
            acc[0][1] = fmaf(a0, b1, acc[0][1]);
            acc[1][0] = fmaf(a1, b0, acc[1][0]);
            acc[1][1] = fmaf(a1, b1, acc[1][1]);
        }
    }
}

// T = 1.5 I - 0.5 * (Z @ Y)
__global__ void ns_T_kernel(int cur) {
    const float* Zc = cur ? g_Z2 : g_Z;
    const float* Yc = cur ? g_Y2 : g_Y;
    int i0 = blockIdx.y * 32, j0 = blockIdx.x * 32;
    float acc[2][2] = {{0.f, 0.f}, {0.f, 0.f}};
    small_tile(Zc, Yc, acc, i0, j0, threadIdx.x);
    int tx = threadIdx.x & 15, ty = threadIdx.x >> 4;
#pragma unroll
    for (int r = 0; r < 2; r++)
#pragma unroll
        for (int c = 0; c < 2; c++) {
            int gi = i0 + ty * 2 + r, gj = j0 + tx * 2 + c;
            g_T[gi * C_DIM + gj] = -0.5f * acc[r][c] + ((gi == gj) ? 1.5f : 0.f);
        }
}

// z==0: Ynext = Y @ T ; z==1: Znext = T @ Z
__global__ void ns_dual_kernel(int cur) {
    const float* Yc = cur ? g_Y2 : g_Y;
    const float* Zc = cur ? g_Z2 : g_Z;
    float* Yn = cur ? g_Y : g_Y2;
    float* Zn = cur ? g_Z : g_Z2;
    const float* A;
    const float* B;
    float* O;
    if (blockIdx.z == 0) { A = Yc; B = g_T; O = Yn; }
    else                 { A = g_T; B = Zc; O = Zn; }
    int i0 = blockIdx.y * 32, j0 = blockIdx.x * 32;
    float acc[2][2] = {{0.f, 0.f}, {0.f, 0.f}};
    small_tile(A, B, acc, i0, j0, threadIdx.x);
    int tx = threadIdx.x & 15, ty = threadIdx.x >> 4;
#pragma unroll
    for (int r = 0; r < 2; r++)
#pragma unroll
        for (int c = 0; c < 2; c++)
            O[(i0 + ty * 2 + r) * C_DIM + j0 + tx * 2 + c] = acc[r][c];
}

// ---------------- wm = Z * rsqrt(s); bias = wm @ mean ----------------
__global__ void wm_bias_kernel(int sel) {
    const float* Zf = sel ? g_Z2 : g_Z;
    __shared__ float red[256];
    int c = blockIdx.x, j = threadIdx.x;
    float rs = g_scal[1];
    float w = Zf[c * C_DIM + j] * rs;
    g_wm[c * C_DIM + j] = w;
    red[j] = w * (g_mean[j] * (1.f / (float)M_TOT));
    __syncthreads();
    for (int s = 128; s > 0; s >>= 1) {
        if (j < s) red[j] += red[j + s];
        __syncthreads();
    }
    if (j == 0) g_bias[c] = red[0];
}

// ---------------- apply: out = wm @ X - bias  (per-n GEMM 256 x 4096 x 256) ----------------
__global__ __launch_bounds__(256, 2) void apply_kernel(const float* __restrict__ X,
                                                       float* __restrict__ out) {
    __shared__ __align__(16) float As[8][128];
    __shared__ __align__(16) float Bs[8][128];
    const int c0 = blockIdx.x * 128, l0 = blockIdx.y * 128, n = blockIdx.z;
    const int tid = threadIdx.x;
    const int tx = tid & 15, ty = tid >> 4;
    const int arow = tid >> 1, aseg = tid & 1;
    const int brow = tid >> 5, bseg = tid & 31;

    const float* Ap = g_wm + (c0 + arow) * C_DIM + aseg * 4;
    const float* Bp = X + ((size_t)(n * C_DIM + brow)) * L_DIM + l0 + bseg * 4;

    unsigned long long acc[8][4];
#pragma unroll
    for (int i = 0; i < 8; i++)
#pragma unroll
        for (int p = 0; p < 4; p++) acc[i][p] = 0ull;

    float4 va = *(const float4*)Ap;
    float4 vb = *(const float4*)Bp;
    for (int k0 = 0; k0 < C_DIM; k0 += 8) {
        __syncthreads();
        As[aseg * 4 + 0][arow] = va.x; As[aseg * 4 + 1][arow] = va.y;
        As[aseg * 4 + 2][arow] = va.z; As[aseg * 4 + 3][arow] = va.w;
        *(float4*)&Bs[brow][bseg * 4] = vb;
        __syncthreads();
        if (k0 + 8 < C_DIM) {
            va = *(const float4*)(Ap + k0 + 8);
            vb = *(const float4*)(Bp + (size_t)(k0 + 8) * L_DIM);
        }
        micro_fma(As, Bs, acc, tx, ty);
    }

#pragma unroll
    for (int i = 0; i < 8; i++) {
        int c = c0 + ty * 8 + i;
        float bi = g_bias[c];
        float* orow = out + ((size_t)(n * C_DIM + c)) * L_DIM + l0 + tx;
#pragma unroll
        for (int p = 0; p < 4; p++) {
            float lo, hi;
            UNPACK2(lo, hi, acc[i][p]);
            orow[16 * (2 * p)] = lo - bi;
            orow[16 * (2 * p + 1)] = hi - bi;
        }
    }
}

// ---------------- launch ----------------
extern "C" void kernel_launch(void* const* d_in, const int* in_sizes, int n_in,
                              void* d_out, int out_size) {
    const float* X = (const float*)d_in[0];
    float* out = (float*)d_out;

    zero_kernel<<<256, 256>>>();
    gram_kernel<<<dim3(4, N_DIM), 256>>>(X);
    sigma_finalize_kernel<<<64, 1024>>>();
    trace_kernel<<<1, 256>>>();
    ns_init_kernel<<<64, 1024>>>();
    for (int it = 0; it < NS_ITERS; ++it) {
        ns_T_kernel<<<dim3(8, 8), 256>>>(it & 1);
        ns_dual_kernel<<<dim3(8, 8, 2), 256>>>(it & 1);
    }
    wm_bias_kernel<<<C_DIM, 256>>>(NS_ITERS & 1);
    apply_kernel<<<dim3(2, 32, 64), 256>>>(X, out);
}

// round 2
// speedup vs baseline: 4.7863x; 4.7863x over previous
#include <cuda_runtime.h>
#include <cuda_bf16.h>
#include <cstdint>
#include <cstddef>

#define C_DIM 256
#define L_DIM 4096
#define N_DIM 64
#define M_TOT (N_DIM * L_DIM)   // 262144
#define EPSV 1e-3f
#define NS_ITERS 5

// ---------------- scratch (device globals; no allocation allowed) ----------------
__device__ __nv_bfloat16 g_Xb[(size_t)N_DIM * C_DIM * L_DIM];  // bf16 copy of X
__device__ __nv_bfloat16 g_Wb[C_DIM * C_DIM];                  // bf16 (wm - I)
__device__ float g_mean[C_DIM];                                // raw channel sums
__device__ float g_sigma[C_DIM * C_DIM];
__device__ float g_Y[C_DIM * C_DIM];
__device__ float g_Y2[C_DIM * C_DIM];
__device__ float g_Z[C_DIM * C_DIM];
__device__ float g_Z2[C_DIM * C_DIM];
__device__ float g_T[C_DIM * C_DIM];
__device__ float g_wm[C_DIM * C_DIM];
__device__ float g_bias[C_DIM];
__device__ float g_scal[2];   // [0]=1/s, [1]=rsqrt(s)

// ---------------- low-level helpers ----------------
__device__ __forceinline__ uint32_t smem_u32(const void* p) {
    return (uint32_t)__cvta_generic_to_shared(p);
}
__device__ __forceinline__ void cp16(uint32_t saddr, const void* g) {
    asm volatile("cp.async.cg.shared.global [%0], [%1], 16;\n" :: "r"(saddr), "l"(g));
}
__device__ __forceinline__ void cp_commit() { asm volatile("cp.async.commit_group;\n"); }
template<int N> __device__ __forceinline__ void cp_wait() {
    asm volatile("cp.async.wait_group %0;\n" :: "n"(N));
}
__device__ __forceinline__ void ldsm4(uint32_t r[4], uint32_t a) {
    asm volatile("ldmatrix.sync.aligned.m8n8.x4.shared.b16 {%0,%1,%2,%3}, [%4];"
                 : "=r"(r[0]), "=r"(r[1]), "=r"(r[2]), "=r"(r[3]) : "r"(a));
}
__device__ __forceinline__ void ldsm2(uint32_t r[2], uint32_t a) {
    asm volatile("ldmatrix.sync.aligned.m8n8.x2.shared.b16 {%0,%1}, [%2];"
                 : "=r"(r[0]), "=r"(r[1]) : "r"(a));
}
__device__ __forceinline__ void ldsm2t(uint32_t r[2], uint32_t a) {
    asm volatile("ldmatrix.sync.aligned.m8n8.x2.trans.shared.b16 {%0,%1}, [%2];"
                 : "=r"(r[0]), "=r"(r[1]) : "r"(a));
}
__device__ __forceinline__ void mma_bf16(float d[4], const uint32_t a[4], const uint32_t b[2]) {
    asm volatile("mma.sync.aligned.m16n8k16.row.col.f32.bf16.bf16.f32 "
                 "{%0,%1,%2,%3}, {%4,%5,%6,%7}, {%8,%9}, {%0,%1,%2,%3};"
                 : "+f"(d[0]), "+f"(d[1]), "+f"(d[2]), "+f"(d[3])
                 : "r"(a[0]), "r"(a[1]), "r"(a[2]), "r"(a[3]), "r"(b[0]), "r"(b[1]));
}

// ---------------- zero accumulators (every replay: determinism) ----------------
__global__ void zero_kernel() {
    int idx = blockIdx.x * 256 + threadIdx.x;
    if (idx < C_DIM * C_DIM) g_sigma[idx] = 0.f;
    if (idx < C_DIM) g_mean[idx] = 0.f;
}

// ---------------- convert X -> bf16 + channel sums ----------------
__global__ __launch_bounds__(256) void convert_kernel(const float* __restrict__ X) {
    const int row = blockIdx.x;              // n*C + c
    const int c = row & (C_DIM - 1);
    const float* src = X + (size_t)row * L_DIM;
    __nv_bfloat16* dst = g_Xb + (size_t)row * L_DIM;
    float s = 0.f;
#pragma unroll
    for (int it = 0; it < 4; it++) {
        int i = it * 1024 + threadIdx.x * 4;
        float4 v = *(const float4*)(src + i);
        s += (v.x + v.y) + (v.z + v.w);
        __nv_bfloat162 p0 = __floats2bfloat162_rn(v.x, v.y);
        __nv_bfloat162 p1 = __floats2bfloat162_rn(v.z, v.w);
        uint2 pk = make_uint2(*(uint32_t*)&p0, *(uint32_t*)&p1);
        *(uint2*)(dst + i) = pk;
    }
#pragma unroll
    for (int o = 16; o; o >>= 1) s += __shfl_xor_sync(0xffffffffu, s, o);
    __shared__ float ws[8];
    int lane = threadIdx.x & 31, wid = threadIdx.x >> 5;
    if (lane == 0) ws[wid] = s;
    __syncthreads();
    if (threadIdx.x == 0) {
        float t = 0.f;
#pragma unroll
        for (int i = 0; i < 8; i++) t += ws[i];
        atomicAdd(&g_mean[c], t);
    }
}

// ---------------- Gram: g_sigma += Xb Xb^T (3 quadrants, symmetry) ----------------
#define GSTR 72
__global__ __launch_bounds__(256, 2) void gram_kernel() {
    __shared__ __align__(16) __nv_bfloat16 As[2][128][GSTR];
    __shared__ __align__(16) __nv_bfloat16 Bs[2][128][GSTR];
    const int t = blockIdx.x;                // 0:(0,0) 1:(0,128) 2:(128,128)
    const int n = blockIdx.y;
    const int ci = (t == 2) ? 128 : 0;
    const int cj = (t >= 1) ? 128 : 0;
    const int tid = threadIdx.x;
    const int wid = tid >> 5, lane = tid & 31;
    const int m0 = (wid >> 2) * 64, n0 = (wid & 3) * 32;
    const int lrow = tid >> 1, lcs = (tid & 1) * 32;

    const __nv_bfloat16* Ag = g_Xb + ((size_t)(n * C_DIM + ci + lrow)) * L_DIM + lcs;
    const __nv_bfloat16* Bg = g_Xb + ((size_t)(n * C_DIM + cj + lrow)) * L_DIM + lcs;

    float acc[4][4][4];
#pragma unroll
    for (int i = 0; i < 4; i++)
#pragma unroll
        for (int j = 0; j < 4; j++)
#pragma unroll
            for (int r = 0; r < 4; r++) acc[i][j][r] = 0.f;

    // precompute smem addrs for this thread's loads
    uint32_t sA0 = smem_u32(&As[0][lrow][lcs]);
    uint32_t sB0 = smem_u32(&Bs[0][lrow][lcs]);
    const uint32_t bufstride = 128 * GSTR * 2;

    // prologue: chunk 0
#pragma unroll
    for (int i = 0; i < 4; i++) {
        cp16(sA0 + i * 16, Ag + i * 8);
        cp16(sB0 + i * 16, Bg + i * 8);
    }
    cp_commit();

    for (int c = 0; c < L_DIM / 64; c++) {
        if (c + 1 < L_DIM / 64) {
            int nb = (c + 1) & 1;
            int l0 = (c + 1) * 64;
#pragma unroll
            for (int i = 0; i < 4; i++) {
                cp16(sA0 + nb * bufstride + i * 16, Ag + l0 + i * 8);
                cp16(sB0 + nb * bufstride + i * 16, Bg + l0 + i * 8);
            }
            cp_commit();
            cp_wait<1>();
        } else {
            cp_wait<0>();
        }
        __syncthreads();
        const int buf = c & 1;
#pragma unroll
        for (int ks = 0; ks < 4; ks++) {
            uint32_t af[4][4], bf_[4][2];
#pragma unroll
            for (int i = 0; i < 4; i++)
                ldsm4(af[i], smem_u32(&As[buf][m0 + i * 16 + (lane & 15)][ks * 16 + ((lane >> 4) << 3)]));
#pragma unroll
            for (int j = 0; j < 4; j++)
                ldsm2(bf_[j], smem_u32(&Bs[buf][n0 + j * 8 + (lane & 7)][ks * 16 + (lane & 8)]));
#pragma unroll
            for (int i = 0; i < 4; i++)
#pragma unroll
                for (int j = 0; j < 4; j++) mma_bf16(acc[i][j], af[i], bf_[j]);
        }
        __syncthreads();
    }

    const int r = lane >> 2, cp_ = (lane & 3) * 2;
#pragma unroll
    for (int i = 0; i < 4; i++)
#pragma unroll
        for (int j = 0; j < 4; j++) {
            int gi = ci + m0 + i * 16 + r;
            int gj = cj + n0 + j * 8 + cp_;
            atomicAdd(&g_sigma[gi * C_DIM + gj], acc[i][j][0]);
            atomicAdd(&g_sigma[gi * C_DIM + gj + 1], acc[i][j][1]);
            atomicAdd(&g_sigma[(gi + 8) * C_DIM + gj], acc[i][j][2]);
            atomicAdd(&g_sigma[(gi + 8) * C_DIM + gj + 1], acc[i][j][3]);
        }
}

// ---------------- sigma = gram/m - mean meanT + eps I (+ mirror UR->LL) ----------------
__global__ void sigma_finalize_kernel() {
    int idx = blockIdx.x * 256 + threadIdx.x;   // 3 * 16384
    int q = idx >> 14, rr = idx & 16383;
    int i = ((q == 2) ? 128 : 0) + (rr >> 7);
    int j = ((q >= 1) ? 128 : 0) + (rr & 127);
    const float invm = 1.f / (float)M_TOT;
    float v = g_sigma[i * C_DIM + j] * invm - (g_mean[i] * invm) * (g_mean[j] * invm);
    if (i == j) v += EPSV;
    g_sigma[i * C_DIM + j] = v;
    if (q == 1) g_sigma[j * C_DIM + i] = v;
}

// ---------------- s = trace/C ----------------
__global__ void trace_kernel() {
    __shared__ float red[256];
    int i = threadIdx.x;
    red[i] = g_sigma[i * (C_DIM + 1)];
    __syncthreads();
    for (int s = 128; s > 0; s >>= 1) {
        if (i < s) red[i] += red[i + s];
        __syncthreads();
    }
    if (i == 0) {
        float s = red[0] / (float)C_DIM;
        g_scal[0] = 1.f / s;
        g_scal[1] = rsqrtf(s);
    }
}

__global__ void ns_init_kernel() {
    int idx = blockIdx.x * 1024 + threadIdx.x;
    int i = idx >> 8, j = idx & 255;
    g_Y[idx] = g_sigma[idx] * g_scal[0];
    g_Z[idx] = (i == j) ? 1.f : 0.f;
}

// ---------------- small 256^3 GEMM tile (32x32 per block, 2x2 per thread) ----------------
__device__ __forceinline__ void small_tile(const float* __restrict__ A, const float* __restrict__ B,
                                           float acc[2][2], int i0, int j0, int tid) {
    __shared__ float As[16][32];
    __shared__ float Bs[16][32];
    const int tx = tid & 15, ty = tid >> 4;
    const int ar = tid >> 3, asg = tid & 7;
    const int br = tid >> 4, bsg = tid & 15;
    for (int k0 = 0; k0 < C_DIM; k0 += 16) {
        __syncthreads();
        float2 va = *(const float2*)&A[(i0 + ar) * C_DIM + k0 + asg * 2];
        As[asg * 2 + 0][ar] = va.x;
        As[asg * 2 + 1][ar] = va.y;
        float2 vb = *(const float2*)&B[(k0 + br) * C_DIM + j0 + bsg * 2];
        *(float2*)&Bs[br][bsg * 2] = vb;
        __syncthreads();
#pragma unroll
        for (int k = 0; k < 16; k++) {
            float a0 = As[k][ty * 2], a1 = As[k][ty * 2 + 1];
            float b0 = Bs[k][tx * 2], b1 = Bs[k][tx * 2 + 1];
            acc[0][0] = fmaf(a0, b0, acc[0][0]);
            acc[0][1] = fmaf(a0, b1, acc[0][1]);
            acc[1][0] = fmaf(a1, b0, acc[1][0]);
            acc[1][1] = fmaf(a1, b1, acc[1][1]);
        }
    }
}

__global__ void ns_T_kernel(int cur) {
    const float* Zc = cur ? g_Z2 : g_Z;
    const float* Yc = cur ? g_Y2 : g_Y;
    int i0 = blockIdx.y * 32, j0 = blockIdx.x * 32;
    float acc[2][2] = {{0.f, 0.f}, {0.f, 0.f}};
    small_tile(Zc, Yc, acc, i0, j0, threadIdx.x);
    int tx = threadIdx.x & 15, ty = threadIdx.x >> 4;
#pragma unroll
    for (int r = 0; r < 2; r++)
#pragma unroll
        for (int c = 0; c < 2; c++) {
            int gi = i0 + ty * 2 + r, gj = j0 + tx * 2 + c;
            g_T[gi * C_DIM + gj] = -0.5f * acc[r][c] + ((gi == gj) ? 1.5f : 0.f);
        }
}

__global__ void ns_dual_kernel(int cur) {
    const float* Yc = cur ? g_Y2 : g_Y;
    const float* Zc = cur ? g_Z2 : g_Z;
    float* Yn = cur ? g_Y : g_Y2;
    float* Zn = cur ? g_Z : g_Z2;
    const float* A;
    const float* B;
    float* O;
    if (blockIdx.z == 0) { A = Yc; B = g_T; O = Yn; }
    else                 { A = g_T; B = Zc; O = Zn; }
    int i0 = blockIdx.y * 32, j0 = blockIdx.x * 32;
    float acc[2][2] = {{0.f, 0.f}, {0.f, 0.f}};
    small_tile(A, B, acc, i0, j0, threadIdx.x);
    int tx = threadIdx.x & 15, ty = threadIdx.x >> 4;
#pragma unroll
    for (int r = 0; r < 2; r++)
#pragma unroll
        for (int c = 0; c < 2; c++)
            O[(i0 + ty * 2 + r) * C_DIM + j0 + tx * 2 + c] = acc[r][c];
}

// ---------------- wm = Z*rsqrt(s); Wb = bf16(wm - I); bias = wm @ mean/m ----------------
__global__ void wm_bias_kernel(int sel) {
    const float* Zf = sel ? g_Z2 : g_Z;
    __shared__ float red[256];
    int c = blockIdx.x, j = threadIdx.x;
    float rs = g_scal[1];
    float w = Zf[c * C_DIM + j] * rs;
    g_wm[c * C_DIM + j] = w;
    g_Wb[c * C_DIM + j] = __float2bfloat16(w - ((c == j) ? 1.f : 0.f));
    red[j] = w * (g_mean[j] * (1.f / (float)M_TOT));
    __syncthreads();
    for (int s = 128; s > 0; s >>= 1) {
        if (j < s) red[j] += red[j + s];
        __syncthreads();
    }
    if (j == 0) g_bias[c] = red[0];
}

// ---------------- apply: out = (wm-I)@Xb + X - bias ----------------
#define BSTR 136
__global__ __launch_bounds__(256, 2) void apply_kernel(const float* __restrict__ X,
                                                       float* __restrict__ out) {
    __shared__ __align__(16) __nv_bfloat16 As[2][128][GSTR];   // W-I tile
    __shared__ __align__(16) __nv_bfloat16 Bs[2][64][BSTR];    // Xb tile [k][l]
    const int c0 = blockIdx.x * 128, l0 = blockIdx.y * 128, n = blockIdx.z;
    const int tid = threadIdx.x;
    const int wid = tid >> 5, lane = tid & 31;
    const int m0 = (wid >> 2) * 64, n0 = (wid & 3) * 32;
    const int arow = tid >> 1, acs = (tid & 1) * 32;
    const int brow = tid >> 2, bcs = (tid & 3) * 32;

    const __nv_bfloat16* Ag = g_Wb + (c0 + arow) * C_DIM + acs;
    const __nv_bfloat16* Bg = g_Xb + ((size_t)(n * C_DIM + brow)) * L_DIM + l0 + bcs;

    float acc[4][4][4];
#pragma unroll
    for (int i = 0; i < 4; i++)
#pragma unroll
        for (int j = 0; j < 4; j++)
#pragma unroll
            for (int r = 0; r < 4; r++) acc[i][j][r] = 0.f;

    uint32_t sA0 = smem_u32(&As[0][arow][acs]);
    uint32_t sB0 = smem_u32(&Bs[0][brow][bcs]);
    const uint32_t aStride = 128 * GSTR * 2;
    const uint32_t bStride = 64 * BSTR * 2;

#pragma unroll
    for (int i = 0; i < 4; i++) {
        cp16(sA0 + i * 16, Ag + i * 8);
        cp16(sB0 + i * 16, Bg + i * 8);
    }
    cp_commit();

#pragma unroll 1
    for (int c = 0; c < 4; c++) {
        if (c + 1 < 4) {
            int nb = (c + 1) & 1;
            int k0 = (c + 1) * 64;
#pragma unroll
            for (int i = 0; i < 4; i++) {
                cp16(sA0 + nb * aStride + i * 16, Ag + k0 + i * 8);
                cp16(sB0 + nb * bStride + i * 16, Bg + (size_t)k0 * L_DIM + i * 8);
            }
            cp_commit();
            cp_wait<1>();
        } else {
            cp_wait<0>();
        }
        __syncthreads();
        const int buf = c & 1;
#pragma unroll
        for (int ks = 0; ks < 4; ks++) {
            uint32_t af[4][4], bf_[4][2];
#pragma unroll
            for (int i = 0; i < 4; i++)
                ldsm4(af[i], smem_u32(&As[buf][m0 + i * 16 + (lane & 15)][ks * 16 + ((lane >> 4) << 3)]));
#pragma unroll
            for (int j = 0; j < 4; j++)
                ldsm2t(bf_[j], smem_u32(&Bs[buf][ks * 16 + (lane & 15)][n0 + j * 8]));
#pragma unroll
            for (int i = 0; i < 4; i++)
#pragma unroll
                for (int j = 0; j < 4; j++) mma_bf16(acc[i][j], af[i], bf_[j]);
        }
        __syncthreads();
    }

    const int r = lane >> 2, cp_ = (lane & 3) * 2;
#pragma unroll
    for (int i = 0; i < 4; i++) {
        int c_ = c0 + m0 + i * 16 + r;
        float b0 = g_bias[c_], b1 = g_bias[c_ + 8];
        const float* x0 = X + ((size_t)(n * C_DIM + c_)) * L_DIM + l0;
        const float* x1 = x0 + (size_t)8 * L_DIM;
        float* o0 = out + ((size_t)(n * C_DIM + c_)) * L_DIM + l0;
        float* o1 = o0 + (size_t)8 * L_DIM;
#pragma unroll
        for (int j = 0; j < 4; j++) {
            int l = n0 + j * 8 + cp_;
            float2 xv0 = *(const float2*)(x0 + l);
            float2 xv1 = *(const float2*)(x1 + l);
            float2 ov0 = make_float2(acc[i][j][0] + xv0.x - b0, acc[i][j][1] + xv0.y - b0);
            float2 ov1 = make_float2(acc[i][j][2] + xv1.x - b1, acc[i][j][3] + xv1.y - b1);
            *(float2*)(o0 + l) = ov0;
            *(float2*)(o1 + l) = ov1;
        }
    }
}

// ---------------- launch ----------------
extern "C" void kernel_launch(void* const* d_in, const int* in_sizes, int n_in,
                              void* d_out, int out_size) {
    const float* X = (const float*)d_in[0];
    float* out = (float*)d_out;

    zero_kernel<<<256, 256>>>();
    convert_kernel<<<N_DIM * C_DIM, 256>>>(X);
    gram_kernel<<<dim3(3, N_DIM), 256>>>();
    sigma_finalize_kernel<<<192, 256>>>();
    trace_kernel<<<1, 256>>>();
    ns_init_kernel<<<64, 1024>>>();
    for (int it = 0; it < NS_ITERS; ++it) {
        ns_T_kernel<<<dim3(8, 8), 256>>>(it & 1);
        ns_dual_kernel<<<dim3(8, 8, 2), 256>>>(it & 1);
    }
    wm_bias_kernel<<<C_DIM, 256>>>(NS_ITERS & 1);
    apply_kernel<<<dim3(2, 32, 64), 256>>>(X, out);
}

// round 3
// speedup vs baseline: 5.9063x; 1.2340x over previous
#include <cuda_runtime.h>
#include <cuda_bf16.h>
#include <cstdint>
#include <cstddef>

#define C_DIM 256
#define L_DIM 4096
#define N_DIM 64
#define M_TOT (N_DIM * L_DIM)   // 262144
#define EPSV 1e-3f

// ---------------- scratch (device globals) ----------------
__device__ __nv_bfloat16 g_Wb[C_DIM * C_DIM];   // bf16 (wm - I)
__device__ float g_mean[C_DIM];                 // raw channel sums
__device__ float g_sigma[C_DIM * C_DIM];
__device__ float g_A[C_DIM * C_DIM];
__device__ float g_A2[C_DIM * C_DIM];
__device__ float g_A3[C_DIM * C_DIM];
__device__ float g_A4[C_DIM * C_DIM];
__device__ float g_P0[C_DIM * C_DIM];
__device__ float g_P1[C_DIM * C_DIM];
__device__ float g_bias[C_DIM];
__device__ float g_scal[1];                     // rsqrt(s)

// ---------------- low-level helpers ----------------
__device__ __forceinline__ uint32_t smem_u32(const void* p) {
    return (uint32_t)__cvta_generic_to_shared(p);
}
__device__ __forceinline__ void cp16(uint32_t saddr, const void* g) {
    asm volatile("cp.async.cg.shared.global [%0], [%1], 16;\n" :: "r"(saddr), "l"(g));
}
__device__ __forceinline__ void cp_commit() { asm volatile("cp.async.commit_group;\n"); }
template<int N> __device__ __forceinline__ void cp_wait() {
    asm volatile("cp.async.wait_group %0;\n" :: "n"(N));
}
__device__ __forceinline__ void ldsm4(uint32_t r[4], uint32_t a) {
    asm volatile("ldmatrix.sync.aligned.m8n8.x4.shared.b16 {%0,%1,%2,%3}, [%4];"
                 : "=r"(r[0]), "=r"(r[1]), "=r"(r[2]), "=r"(r[3]) : "r"(a));
}
__device__ __forceinline__ void ldsm2(uint32_t r[2], uint32_t a) {
    asm volatile("ldmatrix.sync.aligned.m8n8.x2.shared.b16 {%0,%1}, [%2];"
                 : "=r"(r[0]), "=r"(r[1]) : "r"(a));
}
__device__ __forceinline__ void ldsm2t(uint32_t r[2], uint32_t a) {
    asm volatile("ldmatrix.sync.aligned.m8n8.x2.trans.shared.b16 {%0,%1}, [%2];"
                 : "=r"(r[0]), "=r"(r[1]) : "r"(a));
}
__device__ __forceinline__ void mma_bf16(float d[4], const uint32_t a[4], const uint32_t b[2]) {
    asm volatile("mma.sync.aligned.m16n8k16.row.col.f32.bf16.bf16.f32 "
                 "{%0,%1,%2,%3}, {%4,%5,%6,%7}, {%8,%9}, {%0,%1,%2,%3};"
                 : "+f"(d[0]), "+f"(d[1]), "+f"(d[2]), "+f"(d[3])
                 : "r"(a[0]), "r"(a[1]), "r"(a[2]), "r"(a[3]), "r"(b[0]), "r"(b[1]));
}
__device__ __forceinline__ uint32_t pk2(float x, float y) {
    __nv_bfloat162 h = __floats2bfloat162_rn(x, y);
    return *(uint32_t*)&h;
}

// shared mma micro-step: 128x128 tile, stride-40 bf16 smem, per-warp 64x32
__device__ __forceinline__ void mma_chunk32(const __nv_bfloat16 (*A)[40], const __nv_bfloat16 (*B)[40],
                                            float acc[4][4][4], int m0, int n0, int lane) {
#pragma unroll
    for (int ks = 0; ks < 2; ks++) {
        uint32_t af[4][4], bq[4][2];
#pragma unroll
        for (int i = 0; i < 4; i++)
            ldsm4(af[i], smem_u32(&A[m0 + i * 16 + (lane & 15)][ks * 16 + ((lane >> 4) << 3)]));
#pragma unroll
        for (int j = 0; j < 4; j++)
            ldsm2(bq[j], smem_u32(&B[n0 + j * 8 + (lane & 7)][ks * 16 + (lane & 8)]));
#pragma unroll
        for (int i = 0; i < 4; i++)
#pragma unroll
            for (int j = 0; j < 4; j++) mma_bf16(acc[i][j], af[i], bq[j]);
    }
}

// ---------------- zero accumulators ----------------
__global__ void zero_kernel() {
    int idx = blockIdx.x * 256 + threadIdx.x;
    g_sigma[idx] = 0.f;
    if (idx < C_DIM) { g_mean[idx] = 0.f; g_bias[idx] = 0.f; }
}

// ---------------- Gram (diag quadrants): fp32 in, in-reg bf16 convert, fused mean ----------------
__global__ __launch_bounds__(256, 2) void gram_diag_kernel(const float* __restrict__ X) {
    __shared__ __align__(16) __nv_bfloat16 As[2][128][40];
    const int ci = blockIdx.x * 128;
    const int n = blockIdx.y, zh = blockIdx.z;
    const int tid = threadIdx.x, wid = tid >> 5, lane = tid & 31;
    const int m0 = (wid >> 2) * 64, n0 = (wid & 3) * 32;
    const int row = tid >> 1, seg = (tid & 1) * 16;
    const float* Ag = X + ((size_t)(n * C_DIM + ci + row)) * L_DIM + zh * 2048 + seg;

    float acc[4][4][4];
#pragma unroll
    for (int i = 0; i < 4; i++)
#pragma unroll
        for (int j = 0; j < 4; j++)
#pragma unroll
            for (int r = 0; r < 4; r++) acc[i][j][r] = 0.f;
    float msum = 0.f;
    float4 pa[4];

#pragma unroll
    for (int q = 0; q < 4; q++) pa[q] = *(const float4*)(Ag + q * 4);
    {
        msum += (pa[0].x + pa[0].y + pa[0].z + pa[0].w) + (pa[1].x + pa[1].y + pa[1].z + pa[1].w)
              + (pa[2].x + pa[2].y + pa[2].z + pa[2].w) + (pa[3].x + pa[3].y + pa[3].z + pa[3].w);
        uint4 lo = make_uint4(pk2(pa[0].x, pa[0].y), pk2(pa[0].z, pa[0].w), pk2(pa[1].x, pa[1].y), pk2(pa[1].z, pa[1].w));
        uint4 hi = make_uint4(pk2(pa[2].x, pa[2].y), pk2(pa[2].z, pa[2].w), pk2(pa[3].x, pa[3].y), pk2(pa[3].z, pa[3].w));
        *(uint4*)&As[0][row][seg] = lo;
        *(uint4*)&As[0][row][seg + 8] = hi;
    }

    for (int c = 0; c < 64; c++) {
        __syncthreads();
        const bool more = (c + 1 < 64);
        if (more) {
#pragma unroll
            for (int q = 0; q < 4; q++) pa[q] = *(const float4*)(Ag + (c + 1) * 32 + q * 4);
        }
        mma_chunk32(As[c & 1], As[c & 1], acc, m0, n0, lane);
        if (more) {
            msum += (pa[0].x + pa[0].y + pa[0].z + pa[0].w) + (pa[1].x + pa[1].y + pa[1].z + pa[1].w)
                  + (pa[2].x + pa[2].y + pa[2].z + pa[2].w) + (pa[3].x + pa[3].y + pa[3].z + pa[3].w);
            uint4 lo = make_uint4(pk2(pa[0].x, pa[0].y), pk2(pa[0].z, pa[0].w), pk2(pa[1].x, pa[1].y), pk2(pa[1].z, pa[1].w));
            uint4 hi = make_uint4(pk2(pa[2].x, pa[2].y), pk2(pa[2].z, pa[2].w), pk2(pa[3].x, pa[3].y), pk2(pa[3].z, pa[3].w));
            int b = (c + 1) & 1;
            *(uint4*)&As[b][row][seg] = lo;
            *(uint4*)&As[b][row][seg + 8] = hi;
        }
    }

    atomicAdd(&g_mean[ci + row], msum);

    const int r = lane >> 2, cpr = (lane & 3) * 2;
#pragma unroll
    for (int i = 0; i < 4; i++)
#pragma unroll
        for (int j = 0; j < 4; j++) {
            int gi = ci + m0 + i * 16 + r;
            int gj = ci + n0 + j * 8 + cpr;
            atomicAdd(&g_sigma[gi * C_DIM + gj], acc[i][j][0]);
            atomicAdd(&g_sigma[gi * C_DIM + gj + 1], acc[i][j][1]);
            atomicAdd(&g_sigma[(gi + 8) * C_DIM + gj], acc[i][j][2]);
            atomicAdd(&g_sigma[(gi + 8) * C_DIM + gj + 1], acc[i][j][3]);
        }
}

// ---------------- Gram (off-diag quadrant ci=0, cj=128) ----------------
__global__ __launch_bounds__(256, 2) void gram_off_kernel(const float* __restrict__ X) {
    __shared__ __align__(16) __nv_bfloat16 As[2][128][40];
    __shared__ __align__(16) __nv_bfloat16 Bs[2][128][40];
    const int n = blockIdx.y, zh = blockIdx.z;
    const int tid = threadIdx.x, wid = tid >> 5, lane = tid & 31;
    const int m0 = (wid >> 2) * 64, n0 = (wid & 3) * 32;
    const int row = tid >> 1, seg = (tid & 1) * 16;
    const float* Ag = X + ((size_t)(n * C_DIM + row)) * L_DIM + zh * 2048 + seg;
    const float* Bg = X + ((size_t)(n * C_DIM + 128 + row)) * L_DIM + zh * 2048 + seg;

    float acc[4][4][4];
#pragma unroll
    for (int i = 0; i < 4; i++)
#pragma unroll
        for (int j = 0; j < 4; j++)
#pragma unroll
            for (int r = 0; r < 4; r++) acc[i][j][r] = 0.f;
    float4 pa[4], pb[4];

#pragma unroll
    for (int q = 0; q < 4; q++) { pa[q] = *(const float4*)(Ag + q * 4); pb[q] = *(const float4*)(Bg + q * 4); }
    {
        uint4 alo = make_uint4(pk2(pa[0].x, pa[0].y), pk2(pa[0].z, pa[0].w), pk2(pa[1].x, pa[1].y), pk2(pa[1].z, pa[1].w));
        uint4 ahi = make_uint4(pk2(pa[2].x, pa[2].y), pk2(pa[2].z, pa[2].w), pk2(pa[3].x, pa[3].y), pk2(pa[3].z, pa[3].w));
        uint4 blo = make_uint4(pk2(pb[0].x, pb[0].y), pk2(pb[0].z, pb[0].w), pk2(pb[1].x, pb[1].y), pk2(pb[1].z, pb[1].w));
        uint4 bhi = make_uint4(pk2(pb[2].x, pb[2].y), pk2(pb[2].z, pb[2].w), pk2(pb[3].x, pb[3].y), pk2(pb[3].z, pb[3].w));
        *(uint4*)&As[0][row][seg] = alo; *(uint4*)&As[0][row][seg + 8] = ahi;
        *(uint4*)&Bs[0][row][seg] = blo; *(uint4*)&Bs[0][row][seg + 8] = bhi;
    }

    for (int c = 0; c < 64; c++) {
        __syncthreads();
        const bool more = (c + 1 < 64);
        if (more) {
#pragma unroll
            for (int q = 0; q < 4; q++) {
                pa[q] = *(const float4*)(Ag + (c + 1) * 32 + q * 4);
                pb[q] = *(const float4*)(Bg + (c + 1) * 32 + q * 4);
            }
        }
        mma_chunk32(As[c & 1], Bs[c & 1], acc, m0, n0, lane);
        if (more) {
            int b = (c + 1) & 1;
            uint4 alo = make_uint4(pk2(pa[0].x, pa[0].y), pk2(pa[0].z, pa[0].w), pk2(pa[1].x, pa[1].y), pk2(pa[1].z, pa[1].w));
            uint4 ahi = make_uint4(pk2(pa[2].x, pa[2].y), pk2(pa[2].z, pa[2].w), pk2(pa[3].x, pa[3].y), pk2(pa[3].z, pa[3].w));
            uint4 blo = make_uint4(pk2(pb[0].x, pb[0].y), pk2(pb[0].z, pb[0].w), pk2(pb[1].x, pb[1].y), pk2(pb[1].z, pb[1].w));
            uint4 bhi = make_uint4(pk2(pb[2].x, pb[2].y), pk2(pb[2].z, pb[2].w), pk2(pb[3].x, pb[3].y), pk2(pb[3].z, pb[3].w));
            *(uint4*)&As[b][row][seg] = alo; *(uint4*)&As[b][row][seg + 8] = ahi;
            *(uint4*)&Bs[b][row][seg] = blo; *(uint4*)&Bs[b][row][seg + 8] = bhi;
        }
    }

    const int r = lane >> 2, cpr = (lane & 3) * 2;
#pragma unroll
    for (int i = 0; i < 4; i++)
#pragma unroll
        for (int j = 0; j < 4; j++) {
            int gi = m0 + i * 16 + r;
            int gj = 128 + n0 + j * 8 + cpr;
            atomicAdd(&g_sigma[gi * C_DIM + gj], acc[i][j][0]);
            atomicAdd(&g_sigma[gi * C_DIM + gj + 1], acc[i][j][1]);
            atomicAdd(&g_sigma[(gi + 8) * C_DIM + gj], acc[i][j][2]);
            atomicAdd(&g_sigma[(gi + 8) * C_DIM + gj + 1], acc[i][j][3]);
        }
}

// ---------------- sigma = gram/m - mean meanT + eps I (+ mirror) ----------------
__global__ void sigma_finalize_kernel() {
    int idx = blockIdx.x * 256 + threadIdx.x;   // 3 * 16384
    int q = idx >> 14, rr = idx & 16383;
    int i = ((q == 2) ? 128 : 0) + (rr >> 7);
    int j = ((q >= 1) ? 128 : 0) + (rr & 127);
    const float invm = 1.f / (float)M_TOT;
    float v = g_sigma[i * C_DIM + j] * invm - (g_mean[i] * invm) * (g_mean[j] * invm);
    if (i == j) v += EPSV;
    g_sigma[i * C_DIM + j] = v;
    if (q == 1) g_sigma[j * C_DIM + i] = v;
}

// ---------------- A = sigma/s - I ; s = trace/C (per-block recompute, deterministic) ----------------
__global__ void build_A_kernel() {
    __shared__ float red[256];
    int t = threadIdx.x;
    red[t] = g_sigma[t * (C_DIM + 1)];
    __syncthreads();
    for (int s = 128; s > 0; s >>= 1) {
        if (t < s) red[t] += red[t + s];
        __syncthreads();
    }
    float sv = red[0] / (float)C_DIM;
    float inv = 1.f / sv;
    if (blockIdx.x == 0 && t == 0) g_scal[0] = rsqrtf(sv);
    int base = blockIdx.x * 1024 + t * 4;
#pragma unroll
    for (int q = 0; q < 4; q++) {
        int idx = base + q;
        int i = idx >> 8, j = idx & 255;
        g_A[idx] = g_sigma[idx] * inv - ((i == j) ? 1.f : 0.f);
    }
}

// ---------------- small fp32 64x64-tile GEMM core (K=256) ----------------
__device__ __forceinline__ void small_gemm64(const float* __restrict__ A, const float* __restrict__ B,
                                             float acc[4][4], int i0, int j0) {
    __shared__ float As[16][68];
    __shared__ float Bs[16][68];
    const int tid = threadIdx.x;
    const int tx = tid & 15, ty = tid >> 4;
    const int arow = tid >> 2, akq = (tid & 3) * 4;
    for (int k0 = 0; k0 < C_DIM; k0 += 16) {
        __syncthreads();
        float4 va = *(const float4*)&A[(i0 + arow) * C_DIM + k0 + akq];
        As[akq + 0][arow] = va.x; As[akq + 1][arow] = va.y;
        As[akq + 2][arow] = va.z; As[akq + 3][arow] = va.w;
        float4 vb = *(const float4*)&B[(k0 + ty) * C_DIM + j0 + tx * 4];
        *(float4*)&Bs[ty][tx * 4] = vb;
        __syncthreads();
#pragma unroll
        for (int k = 0; k < 16; k++) {
            float4 a = *(const float4*)&As[k][ty * 4];
            float4 b = *(const float4*)&Bs[k][tx * 4];
            float av[4] = {a.x, a.y, a.z, a.w};
            float bv[4] = {b.x, b.y, b.z, b.w};
#pragma unroll
            for (int r = 0; r < 4; r++)
#pragma unroll
                for (int c = 0; c < 4; c++) acc[r][c] = fmaf(av[r], bv[c], acc[r][c]);
        }
    }
}

// mode 0: A2 = A*A ; mode 1: z0: A3 = A2*A, z1: A4 = A2*A2
__global__ void pgemm_kernel(int mode) {
    const float* A;
    const float* B;
    float* C;
    if (mode == 0) { A = g_A; B = g_A; C = g_A2; }
    else if (blockIdx.z == 0) { A = g_A2; B = g_A; C = g_A3; }
    else { A = g_A2; B = g_A2; C = g_A4; }
    int i0 = blockIdx.y * 64, j0 = blockIdx.x * 64;
    float acc[4][4] = {};
    small_gemm64(A, B, acc, i0, j0);
    int tx = threadIdx.x & 15, ty = threadIdx.x >> 4;
#pragma unroll
    for (int r = 0; r < 4; r++)
        *(float4*)&C[(i0 + ty * 4 + r) * C_DIM + j0 + tx * 4] =
            make_float4(acc[r][0], acc[r][1], acc[r][2], acc[r][3]);
}

// P0 = I + c1 A + c2 A2 + c3 A3 ;  P1 = c4 I + c5 A + c6 A2 + c7 A3 + c8 A4
__global__ void poly_lin_kernel() {
    const float c1 = -0.5f, c2 = 0.375f, c3 = -0.3125f;
    const float c4 = 0.2734375f, c5 = -0.24609375f, c6 = 0.2255859375f;
    const float c7 = -0.20947265625f, c8 = 0.196380615234375f;
    int base = blockIdx.x * 1024 + threadIdx.x * 4;
#pragma unroll
    for (int q = 0; q < 4; q++) {
        int idx = base + q;
        int i = idx >> 8, j = idx & 255;
        float d = (i == j) ? 1.f : 0.f;
        float a = g_A[idx], a2 = g_A2[idx], a3 = g_A3[idx], a4 = g_A4[idx];
        g_P0[idx] = d + c1 * a + c2 * a2 + c3 * a3;
        g_P1[idx] = c4 * d + c5 * a + c6 * a2 + c7 * a3 + c8 * a4;
    }
}

// wm = rs*(P0 + A4*P1) ; Wb = bf16(wm - I) ; bias[i] += wm[i,:]*mean/m
__global__ void final_gemm_kernel() {
    int i0 = blockIdx.y * 64, j0 = blockIdx.x * 64;
    float acc[4][4] = {};
    small_gemm64(g_A4, g_P1, acc, i0, j0);
    int tx = threadIdx.x & 15, ty = threadIdx.x >> 4;
    float rs = g_scal[0];
    const float invm = 1.f / (float)M_TOT;
#pragma unroll
    for (int r = 0; r < 4; r++) {
        int gi = i0 + ty * 4 + r;
        float bsum = 0.f;
#pragma unroll
        for (int c = 0; c < 4; c++) {
            int gj = j0 + tx * 4 + c;
            float w = rs * (g_P0[gi * C_DIM + gj] + acc[r][c]);
            g_Wb[gi * C_DIM + gj] = __float2bfloat16(w - ((gi == gj) ? 1.f : 0.f));
            bsum += w * (g_mean[gj] * invm);
        }
        atomicAdd(&g_bias[gi], bsum);
    }
}

// ---------------- apply: out = (wm-I)@bf16(X) + X - bias ----------------
__global__ __launch_bounds__(256, 2) void apply_kernel(const float* __restrict__ X,
                                                       float* __restrict__ out) {
    __shared__ __align__(16) __nv_bfloat16 As[2][128][40];    // Wb tile [m=128][k=32]
    __shared__ __align__(16) __nv_bfloat16 Bs[2][32][136];    // X tile  [k=32][l=128]
    const int c0 = blockIdx.x * 128, l0 = blockIdx.y * 128, n = blockIdx.z;
    const int tid = threadIdx.x, wid = tid >> 5, lane = tid & 31;
    const int m0 = (wid >> 2) * 64, n0 = (wid & 3) * 32;
    const int arow = tid >> 1, aseg = (tid & 1) * 16;
    const int brow = tid >> 3, bcol = (tid & 7) * 16;

    const __nv_bfloat16* Ag = g_Wb + (c0 + arow) * C_DIM + aseg;
    const float* Bg = X + ((size_t)(n * C_DIM + brow)) * L_DIM + l0 + bcol;

    float acc[4][4][4];
#pragma unroll
    for (int i = 0; i < 4; i++)
#pragma unroll
        for (int j = 0; j < 4; j++)
#pragma unroll
            for (int r = 0; r < 4; r++) acc[i][j][r] = 0.f;

    uint32_t sA0 = smem_u32(&As[0][arow][aseg]);
    const uint32_t aStride = 128 * 40 * 2;
    float4 pb[4];

    cp16(sA0, Ag);
    cp16(sA0 + 16, Ag + 8);
#pragma unroll
    for (int q = 0; q < 4; q++) pb[q] = *(const float4*)(Bg + q * 4);
    cp_commit();
    {
        uint4 lo = make_uint4(pk2(pb[0].x, pb[0].y), pk2(pb[0].z, pb[0].w), pk2(pb[1].x, pb[1].y), pk2(pb[1].z, pb[1].w));
        uint4 hi = make_uint4(pk2(pb[2].x, pb[2].y), pk2(pb[2].z, pb[2].w), pk2(pb[3].x, pb[3].y), pk2(pb[3].z, pb[3].w));
        *(uint4*)&Bs[0][brow][bcol] = lo;
        *(uint4*)&Bs[0][brow][bcol + 8] = hi;
    }

#pragma unroll 1
    for (int c = 0; c < 8; c++) {
        const bool more = (c + 1 < 8);
        if (more) {
            int k0n = (c + 1) * 32;
            int nb = (c + 1) & 1;
            cp16(sA0 + nb * aStride, Ag + k0n);
            cp16(sA0 + nb * aStride + 16, Ag + k0n + 8);
#pragma unroll
            for (int q = 0; q < 4; q++) pb[q] = *(const float4*)(Bg + (size_t)k0n * L_DIM + q * 4);
            cp_commit();
            cp_wait<1>();
        } else {
            cp_wait<0>();
        }
        __syncthreads();
        const int buf = c & 1;
#pragma unroll
        for (int ks = 0; ks < 2; ks++) {
            uint32_t af[4][4], bq[4][2];
#pragma unroll
            for (int i = 0; i < 4; i++)
                ldsm4(af[i], smem_u32(&As[buf][m0 + i * 16 + (lane & 15)][ks * 16 + ((lane >> 4) << 3)]));
#pragma unroll
            for (int j = 0; j < 4; j++)
                ldsm2t(bq[j], smem_u32(&Bs[buf][ks * 16 + (lane & 15)][n0 + j * 8]));
#pragma unroll
            for (int i = 0; i < 4; i++)
#pragma unroll
                for (int j = 0; j < 4; j++) mma_bf16(acc[i][j], af[i], bq[j]);
        }
        if (more) {
            int nb = (c + 1) & 1;
            uint4 lo = make_uint4(pk2(pb[0].x, pb[0].y), pk2(pb[0].z, pb[0].w), pk2(pb[1].x, pb[1].y), pk2(pb[1].z, pb[1].w));
            uint4 hi = make_uint4(pk2(pb[2].x, pb[2].y), pk2(pb[2].z, pb[2].w), pk2(pb[3].x, pb[3].y), pk2(pb[3].z, pb[3].w));
            *(uint4*)&Bs[nb][brow][bcol] = lo;
            *(uint4*)&Bs[nb][brow][bcol + 8] = hi;
        }
    }

    const int r = lane >> 2, cpr = (lane & 3) * 2;
#pragma unroll
    for (int i = 0; i < 4; i++) {
        int c_ = c0 + m0 + i * 16 + r;
        float b0 = g_bias[c_], b1 = g_bias[c_ + 8];
        const float* x0 = X + ((size_t)(n * C_DIM + c_)) * L_DIM + l0;
        const float* x1 = x0 + (size_t)8 * L_DIM;
        float* o0 = out + ((size_t)(n * C_DIM + c_)) * L_DIM + l0;
        float* o1 = o0 + (size_t)8 * L_DIM;
#pragma unroll
        for (int j = 0; j < 4; j++) {
            int l = n0 + j * 8 + cpr;
            float2 xv0 = *(const float2*)(x0 + l);
            float2 xv1 = *(const float2*)(x1 + l);
            float2 ov0 = make_float2(acc[i][j][0] + xv0.x - b0, acc[i][j][1] + xv0.y - b0);
            float2 ov1 = make_float2(acc[i][j][2] + xv1.x - b1, acc[i][j][3] + xv1.y - b1);
            *(float2*)(o0 + l) = ov0;
            *(float2*)(o1 + l) = ov1;
        }
    }
}

// ---------------- launch ----------------
extern "C" void kernel_launch(void* const* d_in, const int* in_sizes, int n_in,
                              void* d_out, int out_size) {
    const float* X = (const float*)d_in[0];
    float* out = (float*)d_out;

    zero_kernel<<<256, 256>>>();
    gram_diag_kernel<<<dim3(2, N_DIM, 2), 256>>>(X);
    gram_off_kernel<<<dim3(1, N_DIM, 2), 256>>>(X);
    sigma_finalize_kernel<<<192, 256>>>();
    build_A_kernel<<<64, 256>>>();
    pgemm_kernel<<<dim3(4, 4), 256>>>(0);
    pgemm_kernel<<<dim3(4, 4, 2), 256>>>(1);
    poly_lin_kernel<<<64, 256>>>();
    final_gemm_kernel<<<dim3(4, 4), 256>>>();
    apply_kernel<<<dim3(2, 32, 64), 256>>>(X, out);
}

// round 4
// speedup vs baseline: 6.6727x; 1.1298x over previous
#include <cuda_runtime.h>
#include <cuda_bf16.h>
#include <cstdint>
#include <cstddef>

#define C_DIM 256
#define L_DIM 4096
#define N_DIM 64
#define M_TOT (N_DIM * L_DIM)   // 262144
#define EPSV 1e-3f

// ---------------- scratch (device globals) ----------------
__device__ __nv_bfloat16 g_Wb[C_DIM * C_DIM];   // bf16 (wm - I)
__device__ float g_mean[C_DIM];                 // raw channel sums
__device__ float g_gram[C_DIM * C_DIM];         // raw X X^T sums
__device__ float g_A[C_DIM * C_DIM];
__device__ float g_A2[C_DIM * C_DIM];
__device__ float g_Q[C_DIM * C_DIM];
__device__ float g_bias[C_DIM];
__device__ float g_scal[2];                     // [0]=rsqrt(s), [1]=1/s

// ---------------- low-level helpers ----------------
__device__ __forceinline__ uint32_t smem_u32(const void* p) {
    return (uint32_t)__cvta_generic_to_shared(p);
}
__device__ __forceinline__ void cp16(uint32_t saddr, const void* g) {
    asm volatile("cp.async.cg.shared.global [%0], [%1], 16;\n" :: "r"(saddr), "l"(g));
}
__device__ __forceinline__ void cp_commit() { asm volatile("cp.async.commit_group;\n"); }
template<int N> __device__ __forceinline__ void cp_wait() {
    asm volatile("cp.async.wait_group %0;\n" :: "n"(N));
}
__device__ __forceinline__ void ldsm4(uint32_t r[4], uint32_t a) {
    asm volatile("ldmatrix.sync.aligned.m8n8.x4.shared.b16 {%0,%1,%2,%3}, [%4];"
                 : "=r"(r[0]), "=r"(r[1]), "=r"(r[2]), "=r"(r[3]) : "r"(a));
}
__device__ __forceinline__ void ldsm2(uint32_t r[2], uint32_t a) {
    asm volatile("ldmatrix.sync.aligned.m8n8.x2.shared.b16 {%0,%1}, [%2];"
                 : "=r"(r[0]), "=r"(r[1]) : "r"(a));
}
__device__ __forceinline__ void ldsm2t(uint32_t r[2], uint32_t a) {
    asm volatile("ldmatrix.sync.aligned.m8n8.x2.trans.shared.b16 {%0,%1}, [%2];"
                 : "=r"(r[0]), "=r"(r[1]) : "r"(a));
}
__device__ __forceinline__ void mma_bf16(float d[4], const uint32_t a[4], const uint32_t b[2]) {
    asm volatile("mma.sync.aligned.m16n8k16.row.col.f32.bf16.bf16.f32 "
                 "{%0,%1,%2,%3}, {%4,%5,%6,%7}, {%8,%9}, {%0,%1,%2,%3};"
                 : "+f"(d[0]), "+f"(d[1]), "+f"(d[2]), "+f"(d[3])
                 : "r"(a[0]), "r"(a[1]), "r"(a[2]), "r"(a[3]), "r"(b[0]), "r"(b[1]));
}
__device__ __forceinline__ uint32_t pk2(float x, float y) {
    __nv_bfloat162 h = __floats2bfloat162_rn(x, y);
    return *(uint32_t*)&h;
}

// mma micro-step over one K=32 chunk; per-warp 64x32 of a 128x128 tile
__device__ __forceinline__ void mma_chunk32(const __nv_bfloat16 (*A)[40], const __nv_bfloat16 (*B)[40],
                                            float acc[4][4][4], int m0, int n0, int lane) {
#pragma unroll
    for (int ks = 0; ks < 2; ks++) {
        uint32_t af[4][4], bq[4][2];
#pragma unroll
        for (int i = 0; i < 4; i++)
            ldsm4(af[i], smem_u32(&A[m0 + i * 16 + (lane & 15)][ks * 16 + ((lane >> 4) << 3)]));
#pragma unroll
        for (int j = 0; j < 4; j++)
            ldsm2(bq[j], smem_u32(&B[n0 + j * 8 + (lane & 7)][ks * 16 + (lane & 8)]));
#pragma unroll
        for (int i = 0; i < 4; i++)
#pragma unroll
            for (int j = 0; j < 4; j++) mma_bf16(acc[i][j], af[i], bq[j]);
    }
}

// ---------------- zero accumulators ----------------
__global__ void zero_kernel() {
    int idx = blockIdx.x * 256 + threadIdx.x;
    g_gram[idx] = 0.f;
    if (idx < C_DIM) { g_mean[idx] = 0.f; g_bias[idx] = 0.f; }
}

// ---------------- merged Gram: 3 quadrants x 64 n x 4 zh, fused mean ----------------
__global__ __launch_bounds__(256, 2) void gram_kernel(const float* __restrict__ X) {
    __shared__ __align__(16) __nv_bfloat16 As[2][128][40];
    __shared__ __align__(16) __nv_bfloat16 Bs[2][128][40];
    const int t = blockIdx.x;                 // 0:(0,0) 1:(0,128) 2:(128,128)
    const int n = blockIdx.y, zh = blockIdx.z;
    const bool offq = (t == 1);
    const bool domean = !offq;
    const int ci = (t == 2) ? 128 : 0;
    const int cj = (t >= 1) ? 128 : 0;
    const int tid = threadIdx.x, wid = tid >> 5, lane = tid & 31;
    const int m0 = (wid >> 2) * 64, n0 = (wid & 3) * 32;
    const int row = tid >> 1, seg = (tid & 1) * 16;

    const float* Ag = X + ((size_t)(n * C_DIM + ci + row)) * L_DIM + zh * 1024 + seg;
    const float* Bg = X + ((size_t)(n * C_DIM + cj + row)) * L_DIM + zh * 1024 + seg;

    float acc[4][4][4];
#pragma unroll
    for (int i = 0; i < 4; i++)
#pragma unroll
        for (int j = 0; j < 4; j++)
#pragma unroll
            for (int r = 0; r < 4; r++) acc[i][j][r] = 0.f;
    float msum = 0.f;
    float4 pa[4], pb[4];

#pragma unroll
    for (int q = 0; q < 4; q++) pa[q] = *(const float4*)(Ag + q * 4);
    if (offq) {
#pragma unroll
        for (int q = 0; q < 4; q++) pb[q] = *(const float4*)(Bg + q * 4);
    }
    {
        if (domean)
            msum += (pa[0].x + pa[0].y + pa[0].z + pa[0].w) + (pa[1].x + pa[1].y + pa[1].z + pa[1].w)
                  + (pa[2].x + pa[2].y + pa[2].z + pa[2].w) + (pa[3].x + pa[3].y + pa[3].z + pa[3].w);
        uint4 lo = make_uint4(pk2(pa[0].x, pa[0].y), pk2(pa[0].z, pa[0].w), pk2(pa[1].x, pa[1].y), pk2(pa[1].z, pa[1].w));
        uint4 hi = make_uint4(pk2(pa[2].x, pa[2].y), pk2(pa[2].z, pa[2].w), pk2(pa[3].x, pa[3].y), pk2(pa[3].z, pa[3].w));
        *(uint4*)&As[0][row][seg] = lo;
        *(uint4*)&As[0][row][seg + 8] = hi;
        if (offq) {
            uint4 blo = make_uint4(pk2(pb[0].x, pb[0].y), pk2(pb[0].z, pb[0].w), pk2(pb[1].x, pb[1].y), pk2(pb[1].z, pb[1].w));
            uint4 bhi = make_uint4(pk2(pb[2].x, pb[2].y), pk2(pb[2].z, pb[2].w), pk2(pb[3].x, pb[3].y), pk2(pb[3].z, pb[3].w));
            *(uint4*)&Bs[0][row][seg] = blo;
            *(uint4*)&Bs[0][row][seg + 8] = bhi;
        }
    }

#pragma unroll 1
    for (int c = 0; c < 32; c++) {
        __syncthreads();
        const bool more = (c + 1 < 32);
        if (more) {
#pragma unroll
            for (int q = 0; q < 4; q++) pa[q] = *(const float4*)(Ag + (c + 1) * 32 + q * 4);
            if (offq) {
#pragma unroll
                for (int q = 0; q < 4; q++) pb[q] = *(const float4*)(Bg + (c + 1) * 32 + q * 4);
            }
        }
        const int buf = c & 1;
        mma_chunk32(As[buf], offq ? Bs[buf] : As[buf], acc, m0, n0, lane);
        if (more) {
            const int nb = (c + 1) & 1;
            if (domean)
                msum += (pa[0].x + pa[0].y + pa[0].z + pa[0].w) + (pa[1].x + pa[1].y + pa[1].z + pa[1].w)
                      + (pa[2].x + pa[2].y + pa[2].z + pa[2].w) + (pa[3].x + pa[3].y + pa[3].z + pa[3].w);
            uint4 lo = make_uint4(pk2(pa[0].x, pa[0].y), pk2(pa[0].z, pa[0].w), pk2(pa[1].x, pa[1].y), pk2(pa[1].z, pa[1].w));
            uint4 hi = make_uint4(pk2(pa[2].x, pa[2].y), pk2(pa[2].z, pa[2].w), pk2(pa[3].x, pa[3].y), pk2(pa[3].z, pa[3].w));
            *(uint4*)&As[nb][row][seg] = lo;
            *(uint4*)&As[nb][row][seg + 8] = hi;
            if (offq) {
                uint4 blo = make_uint4(pk2(pb[0].x, pb[0].y), pk2(pb[0].z, pb[0].w), pk2(pb[1].x, pb[1].y), pk2(pb[1].z, pb[1].w));
                uint4 bhi = make_uint4(pk2(pb[2].x, pb[2].y), pk2(pb[2].z, pb[2].w), pk2(pb[3].x, pb[3].y), pk2(pb[3].z, pb[3].w));
                *(uint4*)&Bs[nb][row][seg] = blo;
                *(uint4*)&Bs[nb][row][seg + 8] = bhi;
            }
        }
    }

    if (domean) atomicAdd(&g_mean[ci + row], msum);

    const int r = lane >> 2, cpr = (lane & 3) * 2;
#pragma unroll
    for (int i = 0; i < 4; i++)
#pragma unroll
        for (int j = 0; j < 4; j++) {
            int gi = ci + m0 + i * 16 + r;
            int gj = cj + n0 + j * 8 + cpr;
            atomicAdd(&g_gram[gi * C_DIM + gj], acc[i][j][0]);
            atomicAdd(&g_gram[gi * C_DIM + gj + 1], acc[i][j][1]);
            atomicAdd(&g_gram[(gi + 8) * C_DIM + gj], acc[i][j][2]);
            atomicAdd(&g_gram[(gi + 8) * C_DIM + gj + 1], acc[i][j][3]);
        }
}

// ---------------- s = trace(sigma)/C from raw gram ----------------
__global__ void trace_kernel() {
    __shared__ float red[256];
    const float invm = 1.f / (float)M_TOT;
    int t = threadIdx.x;
    float mu = g_mean[t] * invm;
    red[t] = g_gram[t * (C_DIM + 1)] * invm - mu * mu + EPSV;
    __syncthreads();
    for (int s = 128; s > 0; s >>= 1) {
        if (t < s) red[t] += red[t + s];
        __syncthreads();
    }
    if (t == 0) {
        float s = red[0] / (float)C_DIM;
        g_scal[0] = rsqrtf(s);
        g_scal[1] = 1.f / s;
    }
}

// ---------------- A = sigma/s - I directly from raw gram (+ mirror) ----------------
__global__ void buildA_kernel() {
    const float invm = 1.f / (float)M_TOT;
    const float invs = g_scal[1];
    int base = blockIdx.x * 1024 + threadIdx.x * 4;
#pragma unroll
    for (int u = 0; u < 4; u++) {
        int idx = base + u;                       // 0 .. 3*16384
        int q = idx >> 14, rr = idx & 16383;
        int i = ((q == 2) ? 128 : 0) + (rr >> 7);
        int j = ((q >= 1) ? 128 : 0) + (rr & 127);
        float sig = g_gram[i * C_DIM + j] * invm - (g_mean[i] * invm) * (g_mean[j] * invm);
        if (i == j) sig += EPSV;
        float v = sig * invs - ((i == j) ? 1.f : 0.f);
        g_A[i * C_DIM + j] = v;
        if (q == 1) g_A[j * C_DIM + i] = v;
    }
}

// ---------------- small fp32 64x64-tile GEMM core (K=256) ----------------
__device__ __forceinline__ void small_gemm64(const float* __restrict__ A, const float* __restrict__ B,
                                             float acc[4][4], int i0, int j0) {
    __shared__ float As[16][68];
    __shared__ float Bs[16][68];
    const int tid = threadIdx.x;
    const int tx = tid & 15, ty = tid >> 4;
    const int arow = tid >> 2, akq = (tid & 3) * 4;
    for (int k0 = 0; k0 < C_DIM; k0 += 16) {
        __syncthreads();
        float4 va = *(const float4*)&A[(i0 + arow) * C_DIM + k0 + akq];
        As[akq + 0][arow] = va.x; As[akq + 1][arow] = va.y;
        As[akq + 2][arow] = va.z; As[akq + 3][arow] = va.w;
        float4 vb = *(const float4*)&B[(k0 + ty) * C_DIM + j0 + tx * 4];
        *(float4*)&Bs[ty][tx * 4] = vb;
        __syncthreads();
#pragma unroll
        for (int k = 0; k < 16; k++) {
            float4 a = *(const float4*)&As[k][ty * 4];
            float4 b = *(const float4*)&Bs[k][tx * 4];
            float av[4] = {a.x, a.y, a.z, a.w};
            float bv[4] = {b.x, b.y, b.z, b.w};
#pragma unroll
            for (int r = 0; r < 4; r++)
#pragma unroll
                for (int c = 0; c < 4; c++) acc[r][c] = fmaf(av[r], bv[c], acc[r][c]);
        }
    }
}

// A2 = A*A ; fused epilogue: Q = c2 I + c3 A + c4 A2
__global__ void pgemm2_kernel() {
    const float c2 = 0.375f, c3 = -0.3125f, c4 = 0.2734375f;
    int i0 = blockIdx.y * 64, j0 = blockIdx.x * 64;
    float acc[4][4] = {};
    small_gemm64(g_A, g_A, acc, i0, j0);
    int tx = threadIdx.x & 15, ty = threadIdx.x >> 4;
#pragma unroll
    for (int r = 0; r < 4; r++) {
        int gi = i0 + ty * 4 + r;
#pragma unroll
        for (int c = 0; c < 4; c++) {
            int gj = j0 + tx * 4 + c;
            float a2 = acc[r][c];
            g_A2[gi * C_DIM + gj] = a2;
            g_Q[gi * C_DIM + gj] = c4 * a2 + c3 * g_A[gi * C_DIM + gj] + ((gi == gj) ? c2 : 0.f);
        }
    }
}

// wm = rs*(I + c1 A + Q@A2) ; Wb = bf16(wm - I) ; bias += wm @ mean/m
__global__ void final_gemm_kernel() {
    const float c1 = -0.5f;
    int i0 = blockIdx.y * 64, j0 = blockIdx.x * 64;
    float acc[4][4] = {};
    small_gemm64(g_Q, g_A2, acc, i0, j0);
    int tx = threadIdx.x & 15, ty = threadIdx.x >> 4;
    float rs = g_scal[0];
    const float invm = 1.f / (float)M_TOT;
#pragma unroll
    for (int r = 0; r < 4; r++) {
        int gi = i0 + ty * 4 + r;
        float bsum = 0.f;
#pragma unroll
        for (int c = 0; c < 4; c++) {
            int gj = j0 + tx * 4 + c;
            float d = (gi == gj) ? 1.f : 0.f;
            float w = rs * (d + c1 * g_A[gi * C_DIM + gj] + acc[r][c]);
            g_Wb[gi * C_DIM + gj] = __float2bfloat16(w - d);
            bsum += w * (g_mean[gj] * invm);
        }
        atomicAdd(&g_bias[gi], bsum);
    }
}

// ---------------- apply: out = (wm-I)@bf16(X) + X - bias ; M=256 tile ----------------
#define APPLY_SMEM (2 * 256 * 40 * 2 + 2 * 32 * 136 * 2)   // 58368 bytes
__global__ __launch_bounds__(512, 1) void apply_kernel(const float* __restrict__ X,
                                                       float* __restrict__ out) {
    extern __shared__ __align__(16) char sm[];
    __nv_bfloat16 (*As)[40] = (__nv_bfloat16 (*)[40])sm;             // [2*256][40]
    __nv_bfloat16 (*Bs)[136] = (__nv_bfloat16 (*)[136])(sm + 2 * 256 * 40 * 2);  // [2*32][136]
    const int l0 = blockIdx.x * 128, n = blockIdx.y;
    const int tid = threadIdx.x, wid = tid >> 5, lane = tid & 31;
    const int m0 = (wid >> 2) * 64, n0 = (wid & 3) * 32;             // 16 warps: 4x4
    const int arow = tid >> 1, aseg = (tid & 1) * 16;                // 512 thr -> 256 rows x 32 k
    const int brow = tid >> 4, bcol = (tid & 15) * 8;                // 32 rows x 128 l

    const __nv_bfloat16* Ag = g_Wb + arow * C_DIM + aseg;
    const float* Bg = X + ((size_t)(n * C_DIM + brow)) * L_DIM + l0 + bcol;

    float acc[4][4][4];
#pragma unroll
    for (int i = 0; i < 4; i++)
#pragma unroll
        for (int j = 0; j < 4; j++)
#pragma unroll
            for (int r = 0; r < 4; r++) acc[i][j][r] = 0.f;

    uint32_t sA0 = smem_u32(&As[arow][aseg]);
    const uint32_t aStride = 256 * 40 * 2;
    float4 pb0, pb1;

    cp16(sA0, Ag);
    cp16(sA0 + 16, Ag + 8);
    pb0 = *(const float4*)(Bg);
    pb1 = *(const float4*)(Bg + 4);
    cp_commit();
    *(uint4*)&Bs[brow][bcol] = make_uint4(pk2(pb0.x, pb0.y), pk2(pb0.z, pb0.w),
                                          pk2(pb1.x, pb1.y), pk2(pb1.z, pb1.w));

#pragma unroll 1
    for (int c = 0; c < 8; c++) {
        const bool more = (c + 1 < 8);
        if (more) {
            int k0n = (c + 1) * 32;
            int nb = (c + 1) & 1;
            cp16(sA0 + nb * aStride, Ag + k0n);
            cp16(sA0 + nb * aStride + 16, Ag + k0n + 8);
            pb0 = *(const float4*)(Bg + (size_t)k0n * L_DIM);
            pb1 = *(const float4*)(Bg + (size_t)k0n * L_DIM + 4);
            cp_commit();
            cp_wait<1>();
        } else {
            cp_wait<0>();
        }
        __syncthreads();
        const int buf = c & 1;
#pragma unroll
        for (int ks = 0; ks < 2; ks++) {
            uint32_t af[4][4], bq[4][2];
#pragma unroll
            for (int i = 0; i < 4; i++)
                ldsm4(af[i], smem_u32(&As[buf * 256 + m0 + i * 16 + (lane & 15)][ks * 16 + ((lane >> 4) << 3)]));
#pragma unroll
            for (int j = 0; j < 4; j++)
                ldsm2t(bq[j], smem_u32(&Bs[buf * 32 + ks * 16 + (lane & 15)][n0 + j * 8]));
#pragma unroll
            for (int i = 0; i < 4; i++)
#pragma unroll
                for (int j = 0; j < 4; j++) mma_bf16(acc[i][j], af[i], bq[j]);
        }
        if (more) {
            int nb = (c + 1) & 1;
            *(uint4*)&Bs[nb * 32 + brow][bcol] = make_uint4(pk2(pb0.x, pb0.y), pk2(pb0.z, pb0.w),
                                                            pk2(pb1.x, pb1.y), pk2(pb1.z, pb1.w));
        }
    }

    const int r = lane >> 2, cpr = (lane & 3) * 2;
#pragma unroll
    for (int i = 0; i < 4; i++) {
        int c_ = m0 + i * 16 + r;
        float b0 = g_bias[c_], b1 = g_bias[c_ + 8];
        const float* x0 = X + ((size_t)(n * C_DIM + c_)) * L_DIM + l0;
        const float* x1 = x0 + (size_t)8 * L_DIM;
        float* o0 = out + ((size_t)(n * C_DIM + c_)) * L_DIM + l0;
        float* o1 = o0 + (size_t)8 * L_DIM;
#pragma unroll
        for (int j = 0; j < 4; j++) {
            int l = n0 + j * 8 + cpr;
            float2 xv0 = *(const float2*)(x0 + l);
            float2 xv1 = *(const float2*)(x1 + l);
            float2 ov0 = make_float2(acc[i][j][0] + xv0.x - b0, acc[i][j][1] + xv0.y - b0);
            float2 ov1 = make_float2(acc[i][j][2] + xv1.x - b1, acc[i][j][3] + xv1.y - b1);
            *(float2*)(o0 + l) = ov0;
            *(float2*)(o1 + l) = ov1;
        }
    }
}

// ---------------- launch ----------------
extern "C" void kernel_launch(void* const* d_in, const int* in_sizes, int n_in,
                              void* d_out, int out_size) {
    const float* X = (const float*)d_in[0];
    float* out = (float*)d_out;

    cudaFuncSetAttribute(apply_kernel, cudaFuncAttributeMaxDynamicSharedMemorySize, APPLY_SMEM);

    zero_kernel<<<256, 256>>>();
    gram_kernel<<<dim3(3, N_DIM, 4), 256>>>(X);
    trace_kernel<<<1, 256>>>();
    buildA_kernel<<<48, 256>>>();
    pgemm2_kernel<<<dim3(4, 4), 256>>>();
    final_gemm_kernel<<<dim3(4, 4), 256>>>();
    apply_kernel<<<dim3(32, N_DIM), 512, APPLY_SMEM>>>(X, out);
}